// round 6
// baseline (speedup 1.0000x reference)
#include <cuda_runtime.h>

// Problem constants
#define NB 16
#define NH 32
#define NG 8
#define ND 4096
#define DK 128
#define NM 8192
#define NM1 8193

// Output layout: y [16,4096] | Kc [16,8,8193,128] | Vc [16,8,8193,128]
static const long long KC_OFF = 65536LL;
static const long long VC_OFF = 65536LL + 16LL * 8 * 8193 * 128; // 134299648

// Scratch (device globals — no allocations allowed)
__device__ float g_proj_part[32 * 16 * 48 * 128];
__device__ float g_proj[16 * 48 * 128];   // n<32: q[h], 32..39: k_new[g], 40..47: v_new[g]
__device__ float g_part[128 * 64 * 512];  // per-(b,g,chunk) partial o (4 heads x 128 v)
__device__ float g_stats[128 * 64 * 4];   // per-(b,g,chunk,head) sum of exp(l)
__device__ float g_o[16 * 32 * 128];
__device__ float g_ypart[32 * 16 * 4096];
__device__ unsigned int g_tick_n[48];     // tickets (reset by finishers -> replay-safe)
__device__ unsigned int g_tick_bg[128];
__device__ unsigned int g_tick_y[32];

// ---------------------------------------------------------------------------
// K1: projections (q/k_new/v_new), split over D into 32 chunks of 128.
// grid (48, 32) block 128. Last chunk-block per n reduces + appends cache rows.
// ---------------------------------------------------------------------------
__global__ void k_proj(const float* __restrict__ x,
                       const float* __restrict__ Wq,
                       const float* __restrict__ Wk,
                       const float* __restrict__ Wv,
                       float* __restrict__ out) {
    int n = blockIdx.x;
    int c = blockIdx.y;
    int tid = threadIdx.x;
    int d0 = c * 128;
    const float* W = (n < 32) ? (Wq + (size_t)n * ND * DK)
                   : (n < 40) ? (Wk + (size_t)(n - 32) * ND * DK)
                              : (Wv + (size_t)(n - 40) * ND * DK);
    __shared__ float xs[16 * 128];
    for (int idx = tid; idx < 16 * 128; idx += 128) {
        int b = idx >> 7, d = idx & 127;
        xs[idx] = x[b * ND + d0 + d];
    }
    __syncthreads();
    float acc[16];
#pragma unroll
    for (int b = 0; b < 16; b++) acc[b] = 0.f;
#pragma unroll 2
    for (int d = 0; d < 128; d += 4) {
        float w0 = W[(size_t)(d0 + d + 0) * DK + tid];
        float w1 = W[(size_t)(d0 + d + 1) * DK + tid];
        float w2 = W[(size_t)(d0 + d + 2) * DK + tid];
        float w3 = W[(size_t)(d0 + d + 3) * DK + tid];
#pragma unroll
        for (int b = 0; b < 16; b++) {
            float4 xv = *(const float4*)&xs[b * 128 + d];
            acc[b] += xv.x * w0 + xv.y * w1 + xv.z * w2 + xv.w * w3;
        }
    }
#pragma unroll
    for (int b = 0; b < 16; b++)
        g_proj_part[((c * 16 + b) * 48 + n) * 128 + tid] = acc[b];

    // ---- ticket (writes -> fence -> SYNC -> atomic): last block reduces ----
    __threadfence();
    __syncthreads();
    __shared__ unsigned int isLast;
    if (tid == 0) isLast = (atomicAdd(&g_tick_n[n], 1) == 31);
    __syncthreads();
    if (!isLast) return;
    if (tid == 0) g_tick_n[n] = 0;
    for (int b = 0; b < 16; b++) {
        float s = 0.f;
#pragma unroll
        for (int cc = 0; cc < 32; cc++)
            s += __ldcg(&g_proj_part[((cc * 16 + b) * 48 + n) * 128 + tid]);
        g_proj[(b * 48 + n) * 128 + tid] = s;
        if (n >= 32 && n < 40)
            out[KC_OFF + ((long long)(b * 8 + n - 32) * NM1 + NM) * 128 + tid] = s;
        else if (n >= 40)
            out[VC_OFF + ((long long)(b * 8 + n - 40) * NM1 + NM) * 128 + tid] = s;
    }
}

// ---------------------------------------------------------------------------
// K2 (fused): single pass per (b,g,chunk): stream K&V -> Kc/Vc, logits via
// warp reduce, e = exp(logit) (bounded logits, no running max), accumulate
// s and e*V. 1-deep software prefetch; q kept in smem to fit 4 blocks/SM.
// Last chunk-block per (b,g) runs the combine -> g_o.
// ---------------------------------------------------------------------------
__global__ void __launch_bounds__(256, 4)
k_fused(const float* __restrict__ prevK,
        const float* __restrict__ prevV,
        float* __restrict__ out) {
    int bg = blockIdx.x >> 6;
    int chunk = blockIdx.x & 63;
    int b = bg >> 3, g = bg & 7;
    int tid = threadIdx.x, warp = tid >> 5, lane = tid & 31;
    int m0 = chunk * 128;

    __shared__ __align__(16) float qs[512];   // q for heads ri*8+g
    for (int idx = tid; idx < 512; idx += 256) {
        int ri = idx >> 7, k = idx & 127;
        qs[idx] = g_proj[(b * 48 + ri * 8 + g) * 128 + k];
    }
    __syncthreads();
    const float4* qs4 = (const float4*)qs;

    const float4* srcK = (const float4*)(prevK + ((size_t)bg * NM + m0) * 128);
    const float4* srcV = (const float4*)(prevV + ((size_t)bg * NM + m0) * 128);
    float4* dstK = (float4*)(out + KC_OFF + ((long long)bg * NM1 + m0) * 128);
    float4* dstV = (float4*)(out + VC_OFF + ((long long)bg * NM1 + m0) * 128);

    float4 a0 = {0, 0, 0, 0}, a1 = a0, a2 = a0, a3 = a0;
    float s0 = 0.f, s1 = 0.f, s2 = 0.f, s3 = 0.f;

    int r = warp;
    float4 kv = __ldcs(srcK + r * 32 + lane);
    float4 vv = __ldcs(srcV + r * 32 + lane);
#pragma unroll
    for (int it = 0; it < 16; it++) {
        float4 kn = {0, 0, 0, 0}, vn = {0, 0, 0, 0};
        if (it < 15) {                        // prefetch next row
            kn = __ldcs(srcK + (r + 8) * 32 + lane);
            vn = __ldcs(srcV + (r + 8) * 32 + lane);
        }
        __stcs(dstK + r * 32 + lane, kv);
        __stcs(dstV + r * 32 + lane, vv);
        float4 q0 = qs4[lane], q1 = qs4[32 + lane], q2 = qs4[64 + lane], q3 = qs4[96 + lane];
        float l0 = kv.x * q0.x + kv.y * q0.y + kv.z * q0.z + kv.w * q0.w;
        float l1 = kv.x * q1.x + kv.y * q1.y + kv.z * q1.z + kv.w * q1.w;
        float l2 = kv.x * q2.x + kv.y * q2.y + kv.z * q2.z + kv.w * q2.w;
        float l3 = kv.x * q3.x + kv.y * q3.y + kv.z * q3.z + kv.w * q3.w;
#pragma unroll
        for (int off = 16; off > 0; off >>= 1) {
            l0 += __shfl_xor_sync(0xffffffffu, l0, off);
            l1 += __shfl_xor_sync(0xffffffffu, l1, off);
            l2 += __shfl_xor_sync(0xffffffffu, l2, off);
            l3 += __shfl_xor_sync(0xffffffffu, l3, off);
        }
        float e0 = __expf(l0), e1 = __expf(l1), e2 = __expf(l2), e3 = __expf(l3);
        s0 += e0; s1 += e1; s2 += e2; s3 += e3;
        a0.x += e0 * vv.x; a0.y += e0 * vv.y; a0.z += e0 * vv.z; a0.w += e0 * vv.w;
        a1.x += e1 * vv.x; a1.y += e1 * vv.y; a1.z += e1 * vv.z; a1.w += e1 * vv.w;
        a2.x += e2 * vv.x; a2.y += e2 * vv.y; a2.z += e2 * vv.z; a2.w += e2 * vv.w;
        a3.x += e3 * vv.x; a3.y += e3 * vv.y; a3.z += e3 * vv.z; a3.w += e3 * vv.w;
        kv = kn; vv = vn; r += 8;
    }

    // Block-level merge of 8 warp partials (reuse qs region is too small; use accs)
    __shared__ __align__(16) float accs[8 * 512];
    __shared__ float ssum[8 * 4];
    float4* ap = (float4*)&accs[warp * 512];
    ap[lane] = a0; ap[32 + lane] = a1; ap[64 + lane] = a2; ap[96 + lane] = a3;
    if (lane == 0) {
        ssum[warp * 4 + 0] = s0; ssum[warp * 4 + 1] = s1;
        ssum[warp * 4 + 2] = s2; ssum[warp * 4 + 3] = s3;
    }
    __syncthreads();
    size_t pbase = ((size_t)bg * 64 + chunk) * 512;
    for (int idx = tid; idx < 512; idx += 256) {
        float s = 0.f;
#pragma unroll
        for (int w = 0; w < 8; w++) s += accs[w * 512 + idx];
        g_part[pbase + idx] = s;
    }
    if (tid < 4) {
        float t = 0.f;
#pragma unroll
        for (int w = 0; w < 8; w++) t += ssum[w * 4 + tid];
        g_stats[((size_t)bg * 64 + chunk) * 4 + tid] = t;
    }

    // ---- ticket (writes -> fence -> SYNC -> atomic): last block combines ----
    __threadfence();
    __syncthreads();
    __shared__ unsigned int isLast;
    if (tid == 0) isLast = (atomicAdd(&g_tick_bg[bg], 1) == 63);
    __syncthreads();
    if (!isLast) return;
    if (tid == 0) g_tick_bg[bg] = 0;

    __shared__ float s_en[4], s_den[4];
    if (warp < 4) {   // new-token logit per head ri = warp
        float4 qq = qs4[warp * 32 + lane];
        float4 kk = *(const float4*)&g_proj[(b * 48 + 32 + g) * 128 + lane * 4];
        float p = qq.x * kk.x + qq.y * kk.y + qq.z * kk.z + qq.w * kk.w;
#pragma unroll
        for (int off = 16; off > 0; off >>= 1)
            p += __shfl_xor_sync(0xffffffffu, p, off);
        if (lane == 0) s_en[warp] = __expf(p);
    }
    __syncthreads();
    if (tid < 4) {
        float den = s_en[tid];
#pragma unroll 8
        for (int c2 = 0; c2 < 64; c2++)
            den += __ldcg(&g_stats[((size_t)bg * 64 + c2) * 4 + tid]);
        s_den[tid] = den;
    }
    __syncthreads();
    for (int idx = tid; idx < 512; idx += 256) {
        int ri = idx >> 7, v = idx & 127;
        float acc = s_en[ri] * g_proj[(b * 48 + 40 + g) * 128 + v];
        size_t base = (size_t)bg * 64 * 512 + idx;
#pragma unroll 8
        for (int c2 = 0; c2 < 64; c2++)
            acc += __ldcg(&g_part[base + (size_t)c2 * 512]);
        g_o[(b * 32 + ri * 8 + g) * 128 + v] = acc / s_den[ri];
    }
}

// ---------------------------------------------------------------------------
// K3: y[b,d] = sum_hv o[b,hv] * Wo[hv,d], split over hv into 32 chunks of 128.
// grid (32, 32) block 128. Last chunk-block per d0 reduces + writes y.
// ---------------------------------------------------------------------------
__global__ void k_y(const float* __restrict__ Wo, float* __restrict__ out) {
    int d0 = blockIdx.x * 128;
    int c = blockIdx.y;
    int hv0 = c * 128;
    int tid = threadIdx.x;
    __shared__ float os[16 * 128];
    for (int idx = tid; idx < 2048; idx += 128) {
        int b = idx >> 7, j = idx & 127;
        os[idx] = g_o[b * 4096 + hv0 + j];
    }
    __syncthreads();
    float acc[16];
#pragma unroll
    for (int b = 0; b < 16; b++) acc[b] = 0.f;
#pragma unroll 2
    for (int j = 0; j < 128; j += 4) {
        float w0 = Wo[(size_t)(hv0 + j + 0) * 4096 + d0 + tid];
        float w1 = Wo[(size_t)(hv0 + j + 1) * 4096 + d0 + tid];
        float w2 = Wo[(size_t)(hv0 + j + 2) * 4096 + d0 + tid];
        float w3 = Wo[(size_t)(hv0 + j + 3) * 4096 + d0 + tid];
#pragma unroll
        for (int b = 0; b < 16; b++) {
            float4 ov = *(const float4*)&os[b * 128 + j];
            acc[b] += ov.x * w0 + ov.y * w1 + ov.z * w2 + ov.w * w3;
        }
    }
#pragma unroll
    for (int b = 0; b < 16; b++)
        g_ypart[(c * 16 + b) * 4096 + d0 + tid] = acc[b];

    // ---- ticket (writes -> fence -> SYNC -> atomic): last block writes y ----
    __threadfence();
    __syncthreads();
    __shared__ unsigned int isLast;
    if (tid == 0) isLast = (atomicAdd(&g_tick_y[blockIdx.x], 1) == 31);
    __syncthreads();
    if (!isLast) return;
    if (tid == 0) g_tick_y[blockIdx.x] = 0;
    for (int b = 0; b < 16; b++) {
        float s = 0.f;
#pragma unroll
        for (int cc = 0; cc < 32; cc++)
            s += __ldcg(&g_ypart[(cc * 16 + b) * 4096 + d0 + tid]);
        out[b * ND + d0 + tid] = s;
    }
}

extern "C" void kernel_launch(void* const* d_in, const int* in_sizes, int n_in,
                              void* d_out, int out_size) {
    const float* x     = (const float*)d_in[0];
    const float* prevK = (const float*)d_in[1];
    const float* prevV = (const float*)d_in[2];
    const float* Wq    = (const float*)d_in[3];
    const float* Wk    = (const float*)d_in[4];
    const float* Wv    = (const float*)d_in[5];
    const float* Wo    = (const float*)d_in[6];
    float* out = (float*)d_out;

    k_proj<<<dim3(48, 32), 128>>>(x, Wq, Wk, Wv, out);
    k_fused<<<128 * 64, 256>>>(prevK, prevV, out);
    k_y<<<dim3(32, 32), 128>>>(Wo, out);
}

// round 7
// speedup vs baseline: 1.0082x; 1.0082x over previous
#include <cuda_runtime.h>

// Problem constants
#define NB 16
#define NH 32
#define NG 8
#define ND 4096
#define DK 128
#define NM 8192
#define NM1 8193

// Output layout: y [16,4096] | Kc [16,8,8193,128] | Vc [16,8,8193,128]
static const long long KC_OFF = 65536LL;
static const long long VC_OFF = 65536LL + 16LL * 8 * 8193 * 128; // 134299648

// Packed f32x2 helpers (sm_103a)
__device__ __forceinline__ unsigned long long pack2(float lo, float hi) {
    unsigned long long r;
    asm("mov.b64 %0, {%1, %2};" : "=l"(r) : "f"(lo), "f"(hi));
    return r;
}
__device__ __forceinline__ unsigned long long fma2(unsigned long long a,
                                                   unsigned long long b,
                                                   unsigned long long c) {
    unsigned long long d;
    asm("fma.rn.f32x2 %0, %1, %2, %3;" : "=l"(d) : "l"(a), "l"(b), "l"(c));
    return d;
}
__device__ __forceinline__ float hadd2(unsigned long long p) {
    float lo, hi;
    asm("mov.b64 {%0, %1}, %2;" : "=f"(lo), "=f"(hi) : "l"(p));
    return lo + hi;
}

// Scratch (device globals — no allocations allowed)
__device__ float g_proj_part[16 * 16 * 48 * 128];
__device__ float g_proj[16 * 48 * 128];   // n<32: q[h], 32..39: k_new[g], 40..47: v_new[g]
__device__ float g_part[128 * 64 * 512];  // per-(b,g,chunk) partial o (4 heads x 128 v)
__device__ float g_stats[128 * 64 * 4];   // per-(b,g,chunk,head) sum of exp(l)
__device__ float g_o[16 * 32 * 128];
__device__ float g_ypart[16 * 16 * 4096];
__device__ unsigned int g_tick_n[48];     // tickets (reset by finishers -> replay-safe)
__device__ unsigned int g_tick_bg[128];
__device__ unsigned int g_tick_y[32];

// ---------------------------------------------------------------------------
// K1: projections (q/k_new/v_new), split over D into 16 chunks of 256.
// grid (48, 16) block 128. Packed f32x2 FMA: acc lanes = (even-d, odd-d) sums.
// Last chunk-block per n reduces + appends cache rows.
// ---------------------------------------------------------------------------
__global__ void k_proj(const float* __restrict__ x,
                       const float* __restrict__ Wq,
                       const float* __restrict__ Wk,
                       const float* __restrict__ Wv,
                       float* __restrict__ out) {
    int n = blockIdx.x;
    int c = blockIdx.y;
    int tid = threadIdx.x;
    int d0 = c * 256;
    const float* W = (n < 32) ? (Wq + (size_t)n * ND * DK)
                   : (n < 40) ? (Wk + (size_t)(n - 32) * ND * DK)
                              : (Wv + (size_t)(n - 40) * ND * DK);
    __shared__ __align__(16) float xs[16 * 256];
    for (int idx = tid; idx < 16 * 256; idx += 128) {
        int b = idx >> 8, d = idx & 255;
        xs[idx] = x[b * ND + d0 + d];
    }
    __syncthreads();
    unsigned long long accp[16];
#pragma unroll
    for (int b = 0; b < 16; b++) accp[b] = 0ull;
    for (int d = 0; d < 256; d += 4) {
        float w0 = W[(size_t)(d0 + d + 0) * DK + tid];
        float w1 = W[(size_t)(d0 + d + 1) * DK + tid];
        float w2 = W[(size_t)(d0 + d + 2) * DK + tid];
        float w3 = W[(size_t)(d0 + d + 3) * DK + tid];
        unsigned long long wp01 = pack2(w0, w1);
        unsigned long long wp23 = pack2(w2, w3);
#pragma unroll
        for (int b = 0; b < 16; b++) {
            unsigned long long x01 = *(const unsigned long long*)&xs[b * 256 + d];
            unsigned long long x23 = *(const unsigned long long*)&xs[b * 256 + d + 2];
            accp[b] = fma2(x01, wp01, accp[b]);
            accp[b] = fma2(x23, wp23, accp[b]);
        }
    }
#pragma unroll
    for (int b = 0; b < 16; b++)
        g_proj_part[((c * 16 + b) * 48 + n) * 128 + tid] = hadd2(accp[b]);

    // ---- ticket (writes -> fence -> SYNC -> atomic): last block reduces ----
    __threadfence();
    __syncthreads();
    __shared__ unsigned int isLast;
    if (tid == 0) isLast = (atomicAdd(&g_tick_n[n], 1) == 15);
    __syncthreads();
    if (!isLast) return;
    if (tid == 0) g_tick_n[n] = 0;
    for (int b = 0; b < 16; b++) {
        float s = 0.f;
#pragma unroll
        for (int cc = 0; cc < 16; cc++)
            s += __ldcg(&g_proj_part[((cc * 16 + b) * 48 + n) * 128 + tid]);
        g_proj[(b * 48 + n) * 128 + tid] = s;
        if (n >= 32 && n < 40)
            out[KC_OFF + ((long long)(b * 8 + n - 32) * NM1 + NM) * 128 + tid] = s;
        else if (n >= 40)
            out[VC_OFF + ((long long)(b * 8 + n - 40) * NM1 + NM) * 128 + tid] = s;
    }
}

// ---------------------------------------------------------------------------
// K2 (fused): single pass per (b,g,chunk): stream K&V -> Kc/Vc, logits via
// warp reduce, e = exp(logit), accumulate s and e*V. Contiguous 16 rows per
// warp, depth-2 software prefetch. Last chunk-block per (b,g) combines.
// ---------------------------------------------------------------------------
__global__ void __launch_bounds__(256, 3)
k_fused(const float* __restrict__ prevK,
        const float* __restrict__ prevV,
        float* __restrict__ out) {
    int bg = blockIdx.x >> 6;
    int chunk = blockIdx.x & 63;
    int b = bg >> 3, g = bg & 7;
    int tid = threadIdx.x, warp = tid >> 5, lane = tid & 31;
    int m0 = chunk * 128;

    float4 q0 = *(const float4*)&g_proj[(b * 48 + 0 * 8 + g) * 128 + lane * 4];
    float4 q1 = *(const float4*)&g_proj[(b * 48 + 1 * 8 + g) * 128 + lane * 4];
    float4 q2 = *(const float4*)&g_proj[(b * 48 + 2 * 8 + g) * 128 + lane * 4];
    float4 q3 = *(const float4*)&g_proj[(b * 48 + 3 * 8 + g) * 128 + lane * 4];

    // warp owns contiguous rows [warp*16, warp*16+16)
    int r0 = warp * 16;
    const float4* srcK = (const float4*)(prevK + ((size_t)bg * NM + m0 + r0) * 128) + lane;
    const float4* srcV = (const float4*)(prevV + ((size_t)bg * NM + m0 + r0) * 128) + lane;
    float4* dstK = (float4*)(out + KC_OFF + ((long long)bg * NM1 + m0 + r0) * 128) + lane;
    float4* dstV = (float4*)(out + VC_OFF + ((long long)bg * NM1 + m0 + r0) * 128) + lane;

    float4 a0 = {0, 0, 0, 0}, a1 = a0, a2 = a0, a3 = a0;
    float s0 = 0.f, s1 = 0.f, s2 = 0.f, s3 = 0.f;
    float es[16];   // per-row weights (kept for g_part path below)

    float4 ka = __ldcs(srcK + 0 * 32), va = __ldcs(srcV + 0 * 32);
    float4 kb = __ldcs(srcK + 1 * 32), vb = __ldcs(srcV + 1 * 32);
#pragma unroll
    for (int i = 0; i < 16; i++) {
        float4 kn = {0, 0, 0, 0}, vn = {0, 0, 0, 0};
        if (i + 2 < 16) {
            kn = __ldcs(srcK + (i + 2) * 32);
            vn = __ldcs(srcV + (i + 2) * 32);
        }
        __stcs(dstK + i * 32, ka);
        __stcs(dstV + i * 32, va);
        float l0 = ka.x * q0.x + ka.y * q0.y + ka.z * q0.z + ka.w * q0.w;
        float l1 = ka.x * q1.x + ka.y * q1.y + ka.z * q1.z + ka.w * q1.w;
        float l2 = ka.x * q2.x + ka.y * q2.y + ka.z * q2.z + ka.w * q2.w;
        float l3 = ka.x * q3.x + ka.y * q3.y + ka.z * q3.z + ka.w * q3.w;
#pragma unroll
        for (int off = 16; off > 0; off >>= 1) {
            l0 += __shfl_xor_sync(0xffffffffu, l0, off);
            l1 += __shfl_xor_sync(0xffffffffu, l1, off);
            l2 += __shfl_xor_sync(0xffffffffu, l2, off);
            l3 += __shfl_xor_sync(0xffffffffu, l3, off);
        }
        float e0 = __expf(l0), e1 = __expf(l1), e2 = __expf(l2), e3 = __expf(l3);
        s0 += e0; s1 += e1; s2 += e2; s3 += e3;
        a0.x += e0 * va.x; a0.y += e0 * va.y; a0.z += e0 * va.z; a0.w += e0 * va.w;
        a1.x += e1 * va.x; a1.y += e1 * va.y; a1.z += e1 * va.z; a1.w += e1 * va.w;
        a2.x += e2 * va.x; a2.y += e2 * va.y; a2.z += e2 * va.z; a2.w += e2 * va.w;
        a3.x += e3 * va.x; a3.y += e3 * va.y; a3.z += e3 * va.z; a3.w += e3 * va.w;
        ka = kb; va = vb; kb = kn; vb = vn;
        (void)es;
    }

    // Block-level merge of 8 warp partials
    __shared__ __align__(16) float accs[8 * 512];
    __shared__ float ssum[8 * 4];
    float4* ap = (float4*)&accs[warp * 512];
    ap[lane] = a0; ap[32 + lane] = a1; ap[64 + lane] = a2; ap[96 + lane] = a3;
    if (lane == 0) {
        ssum[warp * 4 + 0] = s0; ssum[warp * 4 + 1] = s1;
        ssum[warp * 4 + 2] = s2; ssum[warp * 4 + 3] = s3;
    }
    __syncthreads();
    size_t pbase = ((size_t)bg * 64 + chunk) * 512;
    for (int idx = tid; idx < 512; idx += 256) {
        float s = 0.f;
#pragma unroll
        for (int w = 0; w < 8; w++) s += accs[w * 512 + idx];
        g_part[pbase + idx] = s;
    }
    if (tid < 4) {
        float t = 0.f;
#pragma unroll
        for (int w = 0; w < 8; w++) t += ssum[w * 4 + tid];
        g_stats[((size_t)bg * 64 + chunk) * 4 + tid] = t;
    }

    // ---- ticket (writes -> fence -> SYNC -> atomic): last block combines ----
    __threadfence();
    __syncthreads();
    __shared__ unsigned int isLast;
    if (tid == 0) isLast = (atomicAdd(&g_tick_bg[bg], 1) == 63);
    __syncthreads();
    if (!isLast) return;
    if (tid == 0) g_tick_bg[bg] = 0;

    __shared__ float s_en[4], s_den[4];
    if (warp < 4) {   // new-token logit per head ri = warp
        float4 qq = *(const float4*)&g_proj[(b * 48 + warp * 8 + g) * 128 + lane * 4];
        float4 kk = *(const float4*)&g_proj[(b * 48 + 32 + g) * 128 + lane * 4];
        float p = qq.x * kk.x + qq.y * kk.y + qq.z * kk.z + qq.w * kk.w;
#pragma unroll
        for (int off = 16; off > 0; off >>= 1)
            p += __shfl_xor_sync(0xffffffffu, p, off);
        if (lane == 0) s_en[warp] = __expf(p);
    }
    __syncthreads();
    if (tid < 4) {
        float den = s_en[tid];
#pragma unroll 8
        for (int c2 = 0; c2 < 64; c2++)
            den += __ldcg(&g_stats[((size_t)bg * 64 + c2) * 4 + tid]);
        s_den[tid] = den;
    }
    __syncthreads();
    for (int idx = tid; idx < 512; idx += 256) {
        int ri = idx >> 7, v = idx & 127;
        float acc = s_en[ri] * g_proj[(b * 48 + 40 + g) * 128 + v];
        size_t base = (size_t)bg * 64 * 512 + idx;
#pragma unroll 8
        for (int c2 = 0; c2 < 64; c2++)
            acc += __ldcg(&g_part[base + (size_t)c2 * 512]);
        g_o[(b * 32 + ri * 8 + g) * 128 + v] = acc / s_den[ri];
    }
}

// ---------------------------------------------------------------------------
// K3: y[b,d] = sum_hv o[b,hv] * Wo[hv,d], split over hv (16 chunks of 256).
// grid (32, 16) block 128, packed f32x2. Last chunk-block per d0 writes y.
// ---------------------------------------------------------------------------
__global__ void k_y(const float* __restrict__ Wo, float* __restrict__ out) {
    int d0 = blockIdx.x * 128;
    int c = blockIdx.y;
    int hv0 = c * 256;
    int tid = threadIdx.x;
    __shared__ __align__(16) float os[16 * 256];
    for (int idx = tid; idx < 4096; idx += 128) {
        int b = idx >> 8, j = idx & 255;
        os[idx] = g_o[b * 4096 + hv0 + j];
    }
    __syncthreads();
    unsigned long long accp[16];
#pragma unroll
    for (int b = 0; b < 16; b++) accp[b] = 0ull;
    for (int j = 0; j < 256; j += 4) {
        float w0 = Wo[(size_t)(hv0 + j + 0) * 4096 + d0 + tid];
        float w1 = Wo[(size_t)(hv0 + j + 1) * 4096 + d0 + tid];
        float w2 = Wo[(size_t)(hv0 + j + 2) * 4096 + d0 + tid];
        float w3 = Wo[(size_t)(hv0 + j + 3) * 4096 + d0 + tid];
        unsigned long long wp01 = pack2(w0, w1);
        unsigned long long wp23 = pack2(w2, w3);
#pragma unroll
        for (int b = 0; b < 16; b++) {
            unsigned long long o01 = *(const unsigned long long*)&os[b * 256 + j];
            unsigned long long o23 = *(const unsigned long long*)&os[b * 256 + j + 2];
            accp[b] = fma2(o01, wp01, accp[b]);
            accp[b] = fma2(o23, wp23, accp[b]);
        }
    }
#pragma unroll
    for (int b = 0; b < 16; b++)
        g_ypart[(c * 16 + b) * 4096 + d0 + tid] = hadd2(accp[b]);

    // ---- ticket (writes -> fence -> SYNC -> atomic): last block writes y ----
    __threadfence();
    __syncthreads();
    __shared__ unsigned int isLast;
    if (tid == 0) isLast = (atomicAdd(&g_tick_y[blockIdx.x], 1) == 15);
    __syncthreads();
    if (!isLast) return;
    if (tid == 0) g_tick_y[blockIdx.x] = 0;
    for (int b = 0; b < 16; b++) {
        float s = 0.f;
#pragma unroll
        for (int cc = 0; cc < 16; cc++)
            s += __ldcg(&g_ypart[(cc * 16 + b) * 4096 + d0 + tid]);
        out[b * ND + d0 + tid] = s;
    }
}

extern "C" void kernel_launch(void* const* d_in, const int* in_sizes, int n_in,
                              void* d_out, int out_size) {
    const float* x     = (const float*)d_in[0];
    const float* prevK = (const float*)d_in[1];
    const float* prevV = (const float*)d_in[2];
    const float* Wq    = (const float*)d_in[3];
    const float* Wk    = (const float*)d_in[4];
    const float* Wv    = (const float*)d_in[5];
    const float* Wo    = (const float*)d_in[6];
    float* out = (float*)d_out;

    k_proj<<<dim3(48, 16), 128>>>(x, Wq, Wk, Wv, out);
    k_fused<<<128 * 64, 256>>>(prevK, prevV, out);
    k_y<<<dim3(32, 16), 128>>>(Wo, out);
}

// round 9
// speedup vs baseline: 1.0294x; 1.0210x over previous
#include <cuda_runtime.h>
#include <cstdint>

// Problem constants
#define NB 16
#define NH 32
#define NG 8
#define ND 4096
#define DK 128
#define NM 8192
#define NM1 8193

// Output layout: y [16,4096] | Kc [16,8,8193,128] | Vc [16,8,8193,128]
static const long long KC_OFF = 65536LL;
static const long long VC_OFF = 65536LL + 16LL * 8 * 8193 * 128; // 134299648

// Packed f32x2 helpers (sm_103a)
__device__ __forceinline__ unsigned long long pack2(float lo, float hi) {
    unsigned long long r;
    asm("mov.b64 %0, {%1, %2};" : "=l"(r) : "f"(lo), "f"(hi));
    return r;
}
__device__ __forceinline__ unsigned long long fma2(unsigned long long a,
                                                   unsigned long long b,
                                                   unsigned long long c) {
    unsigned long long d;
    asm("fma.rn.f32x2 %0, %1, %2, %3;" : "=l"(d) : "l"(a), "l"(b), "l"(c));
    return d;
}
__device__ __forceinline__ float hadd2(unsigned long long p) {
    float lo, hi;
    asm("mov.b64 {%0, %1}, %2;" : "=f"(lo), "=f"(hi) : "l"(p));
    return lo + hi;
}

// cp.async helpers
__device__ __forceinline__ uint32_t smem_u32(const void* p) {
    uint32_t a;
    asm("{ .reg .u64 t; cvta.to.shared.u64 t, %1; cvt.u32.u64 %0, t; }"
        : "=r"(a) : "l"(p));
    return a;
}
__device__ __forceinline__ void cp16(uint32_t dst, const void* src) {
    asm volatile("cp.async.cg.shared.global [%0], [%1], 16;" :: "r"(dst), "l"(src));
}
__device__ __forceinline__ void cp_commit() {
    asm volatile("cp.async.commit_group;");
}
template <int N> __device__ __forceinline__ void cp_wait() {
    asm volatile("cp.async.wait_group %0;" :: "n"(N));
}

// Scratch (device globals — no allocations allowed)
__device__ float g_proj_part[16 * 16 * 48 * 128];
__device__ float g_proj[16 * 48 * 128];   // n<32: q[h], 32..39: k_new[g], 40..47: v_new[g]
__device__ float g_part[128 * 64 * 512];  // per-(b,g,chunk) partial o (4 heads x 128 v)
__device__ float g_stats[128 * 64 * 4];   // per-(b,g,chunk,head) sum of exp(l)
__device__ float g_o[16 * 32 * 128];
__device__ float g_ypart[16 * 16 * 4096];
__device__ unsigned int g_tick_n[48];     // tickets (reset by finishers -> replay-safe)
__device__ unsigned int g_tick_bg[128];
__device__ unsigned int g_tick_y[32];

// ---------------------------------------------------------------------------
// K1: projections (q/k_new/v_new), split over D into 16 chunks of 256.
// grid (48, 16) block 128, packed f32x2 FMA.
// Last chunk-block per n reduces + appends cache rows.
// ---------------------------------------------------------------------------
__global__ void k_proj(const float* __restrict__ x,
                       const float* __restrict__ Wq,
                       const float* __restrict__ Wk,
                       const float* __restrict__ Wv,
                       float* __restrict__ out) {
    int n = blockIdx.x;
    int c = blockIdx.y;
    int tid = threadIdx.x;
    int d0 = c * 256;
    const float* W = (n < 32) ? (Wq + (size_t)n * ND * DK)
                   : (n < 40) ? (Wk + (size_t)(n - 32) * ND * DK)
                              : (Wv + (size_t)(n - 40) * ND * DK);
    __shared__ __align__(16) float xs[16 * 256];
    for (int idx = tid; idx < 16 * 256; idx += 128) {
        int b = idx >> 8, d = idx & 255;
        xs[idx] = x[b * ND + d0 + d];
    }
    __syncthreads();
    unsigned long long accp[16];
#pragma unroll
    for (int b = 0; b < 16; b++) accp[b] = 0ull;
    for (int d = 0; d < 256; d += 4) {
        float w0 = W[(size_t)(d0 + d + 0) * DK + tid];
        float w1 = W[(size_t)(d0 + d + 1) * DK + tid];
        float w2 = W[(size_t)(d0 + d + 2) * DK + tid];
        float w3 = W[(size_t)(d0 + d + 3) * DK + tid];
        unsigned long long wp01 = pack2(w0, w1);
        unsigned long long wp23 = pack2(w2, w3);
#pragma unroll
        for (int b = 0; b < 16; b++) {
            unsigned long long x01 = *(const unsigned long long*)&xs[b * 256 + d];
            unsigned long long x23 = *(const unsigned long long*)&xs[b * 256 + d + 2];
            accp[b] = fma2(x01, wp01, accp[b]);
            accp[b] = fma2(x23, wp23, accp[b]);
        }
    }
#pragma unroll
    for (int b = 0; b < 16; b++)
        g_proj_part[((c * 16 + b) * 48 + n) * 128 + tid] = hadd2(accp[b]);

    // ---- ticket (writes -> fence -> SYNC -> atomic): last block reduces ----
    __threadfence();
    __syncthreads();
    __shared__ unsigned int isLast;
    if (tid == 0) isLast = (atomicAdd(&g_tick_n[n], 1) == 15);
    __syncthreads();
    if (!isLast) return;
    if (tid == 0) g_tick_n[n] = 0;
    for (int b = 0; b < 16; b++) {
        float s = 0.f;
#pragma unroll
        for (int cc = 0; cc < 16; cc++)
            s += __ldcg(&g_proj_part[((cc * 16 + b) * 48 + n) * 128 + tid]);
        g_proj[(b * 48 + n) * 128 + tid] = s;
        if (n >= 32 && n < 40)
            out[KC_OFF + ((long long)(b * 8 + n - 32) * NM1 + NM) * 128 + tid] = s;
        else if (n >= 40)
            out[VC_OFF + ((long long)(b * 8 + n - 40) * NM1 + NM) * 128 + tid] = s;
    }
}

// ---------------------------------------------------------------------------
// K2 (fused, cp.async pipeline): per (b,g,chunk of 128 rows):
// 8 stages of 16 rows, 2 smem buffers (32KB dynamic). Stage: async K+V rows
// into smem; compute reads smem, stores rows to Kc/Vc (stcs), logits via
// warp reduce, e = exp(logit), accumulates s and e*V.
// The dynamic buffer is REUSED as the 16KB accs region after the pipeline
// (never live simultaneously) -> total smem ~32KB < 48KB default limit.
// Last chunk-block per (b,g) combines -> g_o.
// ---------------------------------------------------------------------------
__global__ void __launch_bounds__(256, 4)
k_fused(const float* __restrict__ prevK,
        const float* __restrict__ prevV,
        float* __restrict__ out) {
    extern __shared__ __align__(16) float dyn[];   // 8192 floats = 32KB
    int bg = blockIdx.x >> 6;
    int chunk = blockIdx.x & 63;
    int b = bg >> 3, g = bg & 7;
    int tid = threadIdx.x, warp = tid >> 5, lane = tid & 31;
    int m0 = chunk * 128;

    float4 q0 = *(const float4*)&g_proj[(b * 48 + 0 * 8 + g) * 128 + lane * 4];
    float4 q1 = *(const float4*)&g_proj[(b * 48 + 1 * 8 + g) * 128 + lane * 4];
    float4 q2 = *(const float4*)&g_proj[(b * 48 + 2 * 8 + g) * 128 + lane * 4];
    float4 q3 = *(const float4*)&g_proj[(b * 48 + 3 * 8 + g) * 128 + lane * 4];

    const float4* srcK = (const float4*)(prevK + ((size_t)bg * NM + m0) * 128);
    const float4* srcV = (const float4*)(prevV + ((size_t)bg * NM + m0) * 128);
    float4* dstK = (float4*)(out + KC_OFF + ((long long)bg * NM1 + m0) * 128);
    float4* dstV = (float4*)(out + VC_OFF + ((long long)bg * NM1 + m0) * 128);

    uint32_t smK = smem_u32(dyn);              // K bufs at dyn[0..4096), V at [4096..8192)
    uint32_t smV = smK + 16384;

    // stage s covers rows [s*16, s*16+16) = 512 float4; each thread copies 2 of K, 2 of V
    auto issue = [&](int s) {
        int sb = s & 1;
        const float4* gk = srcK + s * 512;
        const float4* gv = srcV + s * 512;
        cp16(smK + sb * 8192 + tid * 16, gk + tid);
        cp16(smK + sb * 8192 + (tid + 256) * 16, gk + tid + 256);
        cp16(smV + sb * 8192 + tid * 16, gv + tid);
        cp16(smV + sb * 8192 + (tid + 256) * 16, gv + tid + 256);
    };

    float4 a0 = {0, 0, 0, 0}, a1 = a0, a2 = a0, a3 = a0;
    float s0 = 0.f, s1 = 0.f, s2 = 0.f, s3 = 0.f;

    issue(0); cp_commit();
    issue(1); cp_commit();

#pragma unroll 1
    for (int s = 0; s < 8; s++) {
        if (s == 7) cp_wait<0>(); else cp_wait<1>();
        __syncthreads();
        int sb = s & 1;
        const float4* bk = (const float4*)(dyn + sb * 2048);
        const float4* bv = (const float4*)(dyn + 4096 + sb * 2048);
#pragma unroll
        for (int j = 0; j < 2; j++) {                 // warp handles 2 rows/stage
            int rr = warp * 2 + j;                    // row within stage
            int R = s * 16 + rr;                      // row within chunk
            float4 kv = bk[rr * 32 + lane];
            float4 vv = bv[rr * 32 + lane];
            __stcs(dstK + R * 32 + lane, kv);
            __stcs(dstV + R * 32 + lane, vv);
            float l0 = kv.x * q0.x + kv.y * q0.y + kv.z * q0.z + kv.w * q0.w;
            float l1 = kv.x * q1.x + kv.y * q1.y + kv.z * q1.z + kv.w * q1.w;
            float l2 = kv.x * q2.x + kv.y * q2.y + kv.z * q2.z + kv.w * q2.w;
            float l3 = kv.x * q3.x + kv.y * q3.y + kv.z * q3.z + kv.w * q3.w;
#pragma unroll
            for (int off = 16; off > 0; off >>= 1) {
                l0 += __shfl_xor_sync(0xffffffffu, l0, off);
                l1 += __shfl_xor_sync(0xffffffffu, l1, off);
                l2 += __shfl_xor_sync(0xffffffffu, l2, off);
                l3 += __shfl_xor_sync(0xffffffffu, l3, off);
            }
            float e0 = __expf(l0), e1 = __expf(l1), e2 = __expf(l2), e3 = __expf(l3);
            s0 += e0; s1 += e1; s2 += e2; s3 += e3;
            a0.x += e0 * vv.x; a0.y += e0 * vv.y; a0.z += e0 * vv.z; a0.w += e0 * vv.w;
            a1.x += e1 * vv.x; a1.y += e1 * vv.y; a1.z += e1 * vv.z; a1.w += e1 * vv.w;
            a2.x += e2 * vv.x; a2.y += e2 * vv.y; a2.z += e2 * vv.z; a2.w += e2 * vv.w;
            a3.x += e3 * vv.x; a3.y += e3 * vv.y; a3.z += e3 * vv.z; a3.w += e3 * vv.w;
        }
        __syncthreads();                     // buffer consumed before next issue
        if (s + 2 < 8) { issue(s + 2); cp_commit(); }
    }
    // Pipeline fully drained and all threads synced; dyn[] is now dead ->
    // reuse dyn[0..4096) as the 8x512 accs merge region.
    float* accs = dyn;
    __shared__ float ssum[8 * 4];

    float4* ap = (float4*)&accs[warp * 512];
    ap[lane] = a0; ap[32 + lane] = a1; ap[64 + lane] = a2; ap[96 + lane] = a3;
    if (lane == 0) {
        ssum[warp * 4 + 0] = s0; ssum[warp * 4 + 1] = s1;
        ssum[warp * 4 + 2] = s2; ssum[warp * 4 + 3] = s3;
    }
    __syncthreads();
    size_t pbase = ((size_t)bg * 64 + chunk) * 512;
    for (int idx = tid; idx < 512; idx += 256) {
        float s = 0.f;
#pragma unroll
        for (int w = 0; w < 8; w++) s += accs[w * 512 + idx];
        g_part[pbase + idx] = s;
    }
    if (tid < 4) {
        float t = 0.f;
#pragma unroll
        for (int w = 0; w < 8; w++) t += ssum[w * 4 + tid];
        g_stats[((size_t)bg * 64 + chunk) * 4 + tid] = t;
    }

    // ---- ticket (writes -> fence -> SYNC -> atomic): last block combines ----
    __threadfence();
    __syncthreads();
    __shared__ unsigned int isLast;
    if (tid == 0) isLast = (atomicAdd(&g_tick_bg[bg], 1) == 63);
    __syncthreads();
    if (!isLast) return;
    if (tid == 0) g_tick_bg[bg] = 0;

    __shared__ float s_en[4], s_den[4];
    if (warp < 4) {   // new-token logit per head ri = warp
        float4 qq = *(const float4*)&g_proj[(b * 48 + warp * 8 + g) * 128 + lane * 4];
        float4 kk = *(const float4*)&g_proj[(b * 48 + 32 + g) * 128 + lane * 4];
        float p = qq.x * kk.x + qq.y * kk.y + qq.z * kk.z + qq.w * kk.w;
#pragma unroll
        for (int off = 16; off > 0; off >>= 1)
            p += __shfl_xor_sync(0xffffffffu, p, off);
        if (lane == 0) s_en[warp] = __expf(p);
    }
    __syncthreads();
    if (tid < 4) {
        float den = s_en[tid];
#pragma unroll 8
        for (int c2 = 0; c2 < 64; c2++)
            den += __ldcg(&g_stats[((size_t)bg * 64 + c2) * 4 + tid]);
        s_den[tid] = den;
    }
    __syncthreads();
    for (int idx = tid; idx < 512; idx += 256) {
        int ri = idx >> 7, v = idx & 127;
        float acc = s_en[ri] * g_proj[(b * 48 + 40 + g) * 128 + v];
        size_t base = (size_t)bg * 64 * 512 + idx;
#pragma unroll 8
        for (int c2 = 0; c2 < 64; c2++)
            acc += __ldcg(&g_part[base + (size_t)c2 * 512]);
        g_o[(b * 32 + ri * 8 + g) * 128 + v] = acc / s_den[ri];
    }
}

// ---------------------------------------------------------------------------
// K3: y[b,d] = sum_hv o[b,hv] * Wo[hv,d], split over hv (16 chunks of 256).
// grid (32, 16) block 128, packed f32x2. Last chunk-block per d0 writes y.
// ---------------------------------------------------------------------------
__global__ void k_y(const float* __restrict__ Wo, float* __restrict__ out) {
    int d0 = blockIdx.x * 128;
    int c = blockIdx.y;
    int hv0 = c * 256;
    int tid = threadIdx.x;
    __shared__ __align__(16) float os[16 * 256];
    for (int idx = tid; idx < 4096; idx += 128) {
        int b = idx >> 8, j = idx & 255;
        os[idx] = g_o[b * 4096 + hv0 + j];
    }
    __syncthreads();
    unsigned long long accp[16];
#pragma unroll
    for (int b = 0; b < 16; b++) accp[b] = 0ull;
    for (int j = 0; j < 256; j += 4) {
        float w0 = Wo[(size_t)(hv0 + j + 0) * 4096 + d0 + tid];
        float w1 = Wo[(size_t)(hv0 + j + 1) * 4096 + d0 + tid];
        float w2 = Wo[(size_t)(hv0 + j + 2) * 4096 + d0 + tid];
        float w3 = Wo[(size_t)(hv0 + j + 3) * 4096 + d0 + tid];
        unsigned long long wp01 = pack2(w0, w1);
        unsigned long long wp23 = pack2(w2, w3);
#pragma unroll
        for (int b = 0; b < 16; b++) {
            unsigned long long o01 = *(const unsigned long long*)&os[b * 256 + j];
            unsigned long long o23 = *(const unsigned long long*)&os[b * 256 + j + 2];
            accp[b] = fma2(o01, wp01, accp[b]);
            accp[b] = fma2(o23, wp23, accp[b]);
        }
    }
#pragma unroll
    for (int b = 0; b < 16; b++)
        g_ypart[(c * 16 + b) * 4096 + d0 + tid] = hadd2(accp[b]);

    // ---- ticket (writes -> fence -> SYNC -> atomic): last block writes y ----
    __threadfence();
    __syncthreads();
    __shared__ unsigned int isLast;
    if (tid == 0) isLast = (atomicAdd(&g_tick_y[blockIdx.x], 1) == 15);
    __syncthreads();
    if (!isLast) return;
    if (tid == 0) g_tick_y[blockIdx.x] = 0;
    for (int b = 0; b < 16; b++) {
        float s = 0.f;
#pragma unroll
        for (int cc = 0; cc < 16; cc++)
            s += __ldcg(&g_ypart[(cc * 16 + b) * 4096 + d0 + tid]);
        out[b * ND + d0 + tid] = s;
    }
}

extern "C" void kernel_launch(void* const* d_in, const int* in_sizes, int n_in,
                              void* d_out, int out_size) {
    const float* x     = (const float*)d_in[0];
    const float* prevK = (const float*)d_in[1];
    const float* prevV = (const float*)d_in[2];
    const float* Wq    = (const float*)d_in[3];
    const float* Wk    = (const float*)d_in[4];
    const float* Wv    = (const float*)d_in[5];
    const float* Wo    = (const float*)d_in[6];
    float* out = (float*)d_out;

    k_proj<<<dim3(48, 16), 128>>>(x, Wq, Wk, Wv, out);
    k_fused<<<128 * 64, 256, 32768>>>(prevK, prevV, out);
    k_y<<<dim3(32, 16), 128>>>(Wo, out);
}

// round 10
// speedup vs baseline: 1.0547x; 1.0247x over previous
#include <cuda_runtime.h>
#include <cstdint>

// Problem constants
#define NB 16
#define NH 32
#define NG 8
#define ND 4096
#define DK 128
#define NM 8192
#define NM1 8193

// Output layout: y [16,4096] | Kc [16,8,8193,128] | Vc [16,8,8193,128]
static const long long KC_OFF = 65536LL;
static const long long VC_OFF = 65536LL + 16LL * 8 * 8193 * 128; // 134299648

// Packed f32x2 helpers (sm_103a)
__device__ __forceinline__ unsigned long long pack2(float lo, float hi) {
    unsigned long long r;
    asm("mov.b64 %0, {%1, %2};" : "=l"(r) : "f"(lo), "f"(hi));
    return r;
}
__device__ __forceinline__ unsigned long long fma2(unsigned long long a,
                                                   unsigned long long b,
                                                   unsigned long long c) {
    unsigned long long d;
    asm("fma.rn.f32x2 %0, %1, %2, %3;" : "=l"(d) : "l"(a), "l"(b), "l"(c));
    return d;
}
__device__ __forceinline__ float hadd2(unsigned long long p) {
    float lo, hi;
    asm("mov.b64 {%0, %1}, %2;" : "=f"(lo), "=f"(hi) : "l"(p));
    return lo + hi;
}

// Scratch (device globals — no allocations allowed)
__device__ float g_proj_part[32 * 16 * 48 * 128];
__device__ float g_proj[16 * 48 * 128];   // n<32: q[h], 32..39: k_new[g], 40..47: v_new[g]
__device__ float g_part[128 * 64 * 512];  // per-(b,g,chunk) partial o (4 heads x 128 v)
__device__ float g_stats[128 * 64 * 4];   // per-(b,g,chunk,head) sum of exp(l)
__device__ float g_o[16 * 32 * 128];
__device__ float g_ypart[32 * 16 * 4096];
__device__ unsigned int g_tick_n[48];     // tickets (reset by finishers -> replay-safe)
__device__ unsigned int g_tick_bg[128];
__device__ unsigned int g_tick_y[32];

// ---------------------------------------------------------------------------
// K1: projections (q/k_new/v_new). grid (48,16), block 256 = 2 halves x 128 k.
// Each half covers 128 d-values; block writes 2 of 32 partial chunks.
// Last block per n reduces the 32 partials and appends cache rows.
// ---------------------------------------------------------------------------
__global__ void k_proj(const float* __restrict__ x,
                       const float* __restrict__ Wq,
                       const float* __restrict__ Wk,
                       const float* __restrict__ Wv,
                       float* __restrict__ out) {
    int n = blockIdx.x;
    int c = blockIdx.y;
    int tid = threadIdx.x;
    int half = tid >> 7;          // 0 or 1
    int kk = tid & 127;           // k index
    int d0 = c * 256 + half * 128;
    const float* W = (n < 32) ? (Wq + (size_t)n * ND * DK)
                   : (n < 40) ? (Wk + (size_t)(n - 32) * ND * DK)
                              : (Wv + (size_t)(n - 40) * ND * DK);
    __shared__ __align__(16) float xs[2 * 16 * 128];
    for (int idx = tid; idx < 2 * 16 * 128; idx += 256) {
        int hh = idx >> 11, rem = idx & 2047;
        int b = rem >> 7, d = rem & 127;
        xs[idx] = x[b * ND + c * 256 + hh * 128 + d];
    }
    __syncthreads();
    const float* xh = xs + half * 2048;
    unsigned long long accp[16];
#pragma unroll
    for (int b = 0; b < 16; b++) accp[b] = 0ull;
    for (int d = 0; d < 128; d += 4) {
        float w0 = W[(size_t)(d0 + d + 0) * DK + kk];
        float w1 = W[(size_t)(d0 + d + 1) * DK + kk];
        float w2 = W[(size_t)(d0 + d + 2) * DK + kk];
        float w3 = W[(size_t)(d0 + d + 3) * DK + kk];
        unsigned long long wp01 = pack2(w0, w1);
        unsigned long long wp23 = pack2(w2, w3);
#pragma unroll
        for (int b = 0; b < 16; b++) {
            unsigned long long x01 = *(const unsigned long long*)&xh[b * 128 + d];
            unsigned long long x23 = *(const unsigned long long*)&xh[b * 128 + d + 2];
            accp[b] = fma2(x01, wp01, accp[b]);
            accp[b] = fma2(x23, wp23, accp[b]);
        }
    }
    int cc_out = c * 2 + half;    // 0..31
#pragma unroll
    for (int b = 0; b < 16; b++)
        g_proj_part[((cc_out * 16 + b) * 48 + n) * 128 + kk] = hadd2(accp[b]);

    // ---- ticket (writes -> fence -> SYNC -> atomic): last block reduces ----
    __threadfence();
    __syncthreads();
    __shared__ unsigned int isLast;
    if (tid == 0) isLast = (atomicAdd(&g_tick_n[n], 1) == 15);
    __syncthreads();
    if (!isLast) return;
    if (tid == 0) g_tick_n[n] = 0;
    if (tid < 128) {
        for (int b = 0; b < 16; b++) {
            float s = 0.f;
#pragma unroll
            for (int cc = 0; cc < 32; cc++)
                s += __ldcg(&g_proj_part[((cc * 16 + b) * 48 + n) * 128 + tid]);
            g_proj[(b * 48 + n) * 128 + tid] = s;
            if (n >= 32 && n < 40)
                out[KC_OFF + ((long long)(b * 8 + n - 32) * NM1 + NM) * 128 + tid] = s;
            else if (n >= 40)
                out[VC_OFF + ((long long)(b * 8 + n - 40) * NM1 + NM) * 128 + tid] = s;
        }
    }
}

// ---------------------------------------------------------------------------
// K2 (fused, R5 version): single pass per (b,g,chunk): stream K&V -> Kc/Vc,
// logits via warp reduce, e = exp(logit) (bounded logits), accumulate s and
// e*V. Depth-1 software prefetch. Last chunk-block per (b,g) combines -> g_o.
// ---------------------------------------------------------------------------
__global__ void __launch_bounds__(256, 3)
k_fused(const float* __restrict__ prevK,
        const float* __restrict__ prevV,
        float* __restrict__ out) {
    int bg = blockIdx.x >> 6;
    int chunk = blockIdx.x & 63;
    int b = bg >> 3, g = bg & 7;
    int tid = threadIdx.x, warp = tid >> 5, lane = tid & 31;
    int m0 = chunk * 128;

    float4 q0 = *(const float4*)&g_proj[(b * 48 + 0 * 8 + g) * 128 + lane * 4];
    float4 q1 = *(const float4*)&g_proj[(b * 48 + 1 * 8 + g) * 128 + lane * 4];
    float4 q2 = *(const float4*)&g_proj[(b * 48 + 2 * 8 + g) * 128 + lane * 4];
    float4 q3 = *(const float4*)&g_proj[(b * 48 + 3 * 8 + g) * 128 + lane * 4];

    const float4* srcK = (const float4*)(prevK + ((size_t)bg * NM + m0) * 128);
    const float4* srcV = (const float4*)(prevV + ((size_t)bg * NM + m0) * 128);
    float4* dstK = (float4*)(out + KC_OFF + ((long long)bg * NM1 + m0) * 128);
    float4* dstV = (float4*)(out + VC_OFF + ((long long)bg * NM1 + m0) * 128);

    float4 a0 = {0, 0, 0, 0}, a1 = a0, a2 = a0, a3 = a0;
    float s0 = 0.f, s1 = 0.f, s2 = 0.f, s3 = 0.f;

    int r = warp;
    float4 kv = __ldcs(srcK + r * 32 + lane);
    float4 vv = __ldcs(srcV + r * 32 + lane);
#pragma unroll
    for (int it = 0; it < 16; it++) {
        float4 kn = {0, 0, 0, 0}, vn = {0, 0, 0, 0};
        if (it < 15) {                        // prefetch next row
            kn = __ldcs(srcK + (r + 8) * 32 + lane);
            vn = __ldcs(srcV + (r + 8) * 32 + lane);
        }
        __stcs(dstK + r * 32 + lane, kv);
        __stcs(dstV + r * 32 + lane, vv);
        float l0 = kv.x * q0.x + kv.y * q0.y + kv.z * q0.z + kv.w * q0.w;
        float l1 = kv.x * q1.x + kv.y * q1.y + kv.z * q1.z + kv.w * q1.w;
        float l2 = kv.x * q2.x + kv.y * q2.y + kv.z * q2.z + kv.w * q2.w;
        float l3 = kv.x * q3.x + kv.y * q3.y + kv.z * q3.z + kv.w * q3.w;
#pragma unroll
        for (int off = 16; off > 0; off >>= 1) {
            l0 += __shfl_xor_sync(0xffffffffu, l0, off);
            l1 += __shfl_xor_sync(0xffffffffu, l1, off);
            l2 += __shfl_xor_sync(0xffffffffu, l2, off);
            l3 += __shfl_xor_sync(0xffffffffu, l3, off);
        }
        float e0 = __expf(l0), e1 = __expf(l1), e2 = __expf(l2), e3 = __expf(l3);
        s0 += e0; s1 += e1; s2 += e2; s3 += e3;
        a0.x += e0 * vv.x; a0.y += e0 * vv.y; a0.z += e0 * vv.z; a0.w += e0 * vv.w;
        a1.x += e1 * vv.x; a1.y += e1 * vv.y; a1.z += e1 * vv.z; a1.w += e1 * vv.w;
        a2.x += e2 * vv.x; a2.y += e2 * vv.y; a2.z += e2 * vv.z; a2.w += e2 * vv.w;
        a3.x += e3 * vv.x; a3.y += e3 * vv.y; a3.z += e3 * vv.z; a3.w += e3 * vv.w;
        kv = kn; vv = vn; r += 8;
    }

    // Block-level merge of 8 warp partials
    __shared__ __align__(16) float accs[8 * 512];
    __shared__ float ssum[8 * 4];
    float4* ap = (float4*)&accs[warp * 512];
    ap[lane] = a0; ap[32 + lane] = a1; ap[64 + lane] = a2; ap[96 + lane] = a3;
    if (lane == 0) {
        ssum[warp * 4 + 0] = s0; ssum[warp * 4 + 1] = s1;
        ssum[warp * 4 + 2] = s2; ssum[warp * 4 + 3] = s3;
    }
    __syncthreads();
    size_t pbase = ((size_t)bg * 64 + chunk) * 512;
    for (int idx = tid; idx < 512; idx += 256) {
        float s = 0.f;
#pragma unroll
        for (int w = 0; w < 8; w++) s += accs[w * 512 + idx];
        g_part[pbase + idx] = s;
    }
    if (tid < 4) {
        float t = 0.f;
#pragma unroll
        for (int w = 0; w < 8; w++) t += ssum[w * 4 + tid];
        g_stats[((size_t)bg * 64 + chunk) * 4 + tid] = t;
    }

    // ---- ticket (writes -> fence -> SYNC -> atomic): last block combines ----
    __threadfence();
    __syncthreads();
    __shared__ unsigned int isLast;
    if (tid == 0) isLast = (atomicAdd(&g_tick_bg[bg], 1) == 63);
    __syncthreads();
    if (!isLast) return;
    if (tid == 0) g_tick_bg[bg] = 0;

    __shared__ float s_en[4], s_den[4];
    if (warp < 4) {   // new-token logit per head ri = warp
        float4 qq = *(const float4*)&g_proj[(b * 48 + warp * 8 + g) * 128 + lane * 4];
        float4 kk = *(const float4*)&g_proj[(b * 48 + 32 + g) * 128 + lane * 4];
        float p = qq.x * kk.x + qq.y * kk.y + qq.z * kk.z + qq.w * kk.w;
#pragma unroll
        for (int off = 16; off > 0; off >>= 1)
            p += __shfl_xor_sync(0xffffffffu, p, off);
        if (lane == 0) s_en[warp] = __expf(p);
    }
    __syncthreads();
    if (tid < 4) {
        float den = s_en[tid];
#pragma unroll 8
        for (int c2 = 0; c2 < 64; c2++)
            den += __ldcg(&g_stats[((size_t)bg * 64 + c2) * 4 + tid]);
        s_den[tid] = den;
    }
    __syncthreads();
    for (int idx = tid; idx < 512; idx += 256) {
        int ri = idx >> 7, v = idx & 127;
        float acc = s_en[ri] * g_proj[(b * 48 + 40 + g) * 128 + v];
        size_t base = (size_t)bg * 64 * 512 + idx;
#pragma unroll 8
        for (int c2 = 0; c2 < 64; c2++)
            acc += __ldcg(&g_part[base + (size_t)c2 * 512]);
        g_o[(b * 32 + ri * 8 + g) * 128 + v] = acc / s_den[ri];
    }
}

// ---------------------------------------------------------------------------
// K3: y[b,d] = sum_hv o[b,hv] * Wo[hv,d]. grid (32,16), block 256 = 2 halves
// x 128 d. Each half covers 128 hv-values; block writes 2 of 32 partials.
// Last block per d0 reduces and writes y.
// ---------------------------------------------------------------------------
__global__ void k_y(const float* __restrict__ Wo, float* __restrict__ out) {
    int d0 = blockIdx.x * 128;
    int c = blockIdx.y;
    int tid = threadIdx.x;
    int half = tid >> 7;
    int dd = tid & 127;
    int hv0 = c * 256 + half * 128;
    __shared__ __align__(16) float os[2 * 16 * 128];
    for (int idx = tid; idx < 2 * 16 * 128; idx += 256) {
        int hh = idx >> 11, rem = idx & 2047;
        int b = rem >> 7, j = rem & 127;
        os[idx] = g_o[b * 4096 + c * 256 + hh * 128 + j];
    }
    __syncthreads();
    const float* oh = os + half * 2048;
    unsigned long long accp[16];
#pragma unroll
    for (int b = 0; b < 16; b++) accp[b] = 0ull;
    for (int j = 0; j < 128; j += 4) {
        float w0 = Wo[(size_t)(hv0 + j + 0) * 4096 + d0 + dd];
        float w1 = Wo[(size_t)(hv0 + j + 1) * 4096 + d0 + dd];
        float w2 = Wo[(size_t)(hv0 + j + 2) * 4096 + d0 + dd];
        float w3 = Wo[(size_t)(hv0 + j + 3) * 4096 + d0 + dd];
        unsigned long long wp01 = pack2(w0, w1);
        unsigned long long wp23 = pack2(w2, w3);
#pragma unroll
        for (int b = 0; b < 16; b++) {
            unsigned long long o01 = *(const unsigned long long*)&oh[b * 128 + j];
            unsigned long long o23 = *(const unsigned long long*)&oh[b * 128 + j + 2];
            accp[b] = fma2(o01, wp01, accp[b]);
            accp[b] = fma2(o23, wp23, accp[b]);
        }
    }
    int cc_out = c * 2 + half;
#pragma unroll
    for (int b = 0; b < 16; b++)
        g_ypart[(cc_out * 16 + b) * 4096 + d0 + dd] = hadd2(accp[b]);

    // ---- ticket (writes -> fence -> SYNC -> atomic): last block writes y ----
    __threadfence();
    __syncthreads();
    __shared__ unsigned int isLast;
    if (tid == 0) isLast = (atomicAdd(&g_tick_y[blockIdx.x], 1) == 15);
    __syncthreads();
    if (!isLast) return;
    if (tid == 0) g_tick_y[blockIdx.x] = 0;
    if (tid < 128) {
        for (int b = 0; b < 16; b++) {
            float s = 0.f;
#pragma unroll
            for (int cc = 0; cc < 32; cc++)
                s += __ldcg(&g_ypart[(cc * 16 + b) * 4096 + d0 + tid]);
            out[b * ND + d0 + tid] = s;
        }
    }
}

extern "C" void kernel_launch(void* const* d_in, const int* in_sizes, int n_in,
                              void* d_out, int out_size) {
    const float* x     = (const float*)d_in[0];
    const float* prevK = (const float*)d_in[1];
    const float* prevV = (const float*)d_in[2];
    const float* Wq    = (const float*)d_in[3];
    const float* Wk    = (const float*)d_in[4];
    const float* Wv    = (const float*)d_in[5];
    const float* Wo    = (const float*)d_in[6];
    float* out = (float*)d_out;

    k_proj<<<dim3(48, 16), 256>>>(x, Wq, Wk, Wv, out);
    k_fused<<<128 * 64, 256>>>(prevK, prevV, out);
    k_y<<<dim3(32, 16), 256>>>(Wo, out);
}

// round 11
// speedup vs baseline: 1.1030x; 1.0458x over previous
#include <cuda_runtime.h>
#include <cstdint>

// Problem constants
#define NB 16
#define NH 32
#define NG 8
#define ND 4096
#define DK 128
#define NM 8192
#define NM1 8193

// Output layout: y [16,4096] | Kc [16,8,8193,128] | Vc [16,8,8193,128]
static const long long KC_OFF = 65536LL;
static const long long VC_OFF = 65536LL + 16LL * 8 * 8193 * 128; // 134299648

// Packed f32x2 helpers (sm_103a)
__device__ __forceinline__ unsigned long long pack2(float lo, float hi) {
    unsigned long long r;
    asm("mov.b64 %0, {%1, %2};" : "=l"(r) : "f"(lo), "f"(hi));
    return r;
}
__device__ __forceinline__ unsigned long long fma2(unsigned long long a,
                                                   unsigned long long b,
                                                   unsigned long long c) {
    unsigned long long d;
    asm("fma.rn.f32x2 %0, %1, %2, %3;" : "=l"(d) : "l"(a), "l"(b), "l"(c));
    return d;
}
__device__ __forceinline__ float hadd2(unsigned long long p) {
    float lo, hi;
    asm("mov.b64 {%0, %1}, %2;" : "=f"(lo), "=f"(hi) : "l"(p));
    return lo + hi;
}

// Scratch (device globals — no allocations allowed)
__device__ float g_proj_part[32 * 16 * 48 * 128];
__device__ float g_proj[16 * 48 * 128];   // n<32: q[h], 32..39: k_new[g], 40..47: v_new[g]
__device__ float g_part[128 * 64 * 512];  // per-(b,g,chunk) partial o (4 heads x 128 v)
__device__ float g_stats[128 * 64 * 4];   // per-(b,g,chunk,head) sum of exp(l)
__device__ float g_o[16 * 32 * 128];
__device__ float g_ypart[32 * 16 * 4096];
__device__ unsigned int g_tick_n[48];     // tickets (reset by finishers -> replay-safe)
__device__ unsigned int g_tick_bg[128];
__device__ unsigned int g_tick_y[32];

// ---------------------------------------------------------------------------
// K1: projections (q/k_new/v_new), split over D into 16 chunks of 256.
// grid (48, 16) block 128, packed f32x2 FMA.  (R7 form: measured 56.7us,
// near the f32x2 FMA-issue floor ~48us.)
// Last chunk-block per n reduces + appends cache rows.
// ---------------------------------------------------------------------------
__global__ void k_proj(const float* __restrict__ x,
                       const float* __restrict__ Wq,
                       const float* __restrict__ Wk,
                       const float* __restrict__ Wv,
                       float* __restrict__ out) {
    int n = blockIdx.x;
    int c = blockIdx.y;
    int tid = threadIdx.x;
    int d0 = c * 256;
    const float* W = (n < 32) ? (Wq + (size_t)n * ND * DK)
                   : (n < 40) ? (Wk + (size_t)(n - 32) * ND * DK)
                              : (Wv + (size_t)(n - 40) * ND * DK);
    __shared__ __align__(16) float xs[16 * 256];
    for (int idx = tid; idx < 16 * 256; idx += 128) {
        int b = idx >> 8, d = idx & 255;
        xs[idx] = x[b * ND + d0 + d];
    }
    __syncthreads();
    unsigned long long accp[16];
#pragma unroll
    for (int b = 0; b < 16; b++) accp[b] = 0ull;
    for (int d = 0; d < 256; d += 4) {
        float w0 = W[(size_t)(d0 + d + 0) * DK + tid];
        float w1 = W[(size_t)(d0 + d + 1) * DK + tid];
        float w2 = W[(size_t)(d0 + d + 2) * DK + tid];
        float w3 = W[(size_t)(d0 + d + 3) * DK + tid];
        unsigned long long wp01 = pack2(w0, w1);
        unsigned long long wp23 = pack2(w2, w3);
#pragma unroll
        for (int b = 0; b < 16; b++) {
            unsigned long long x01 = *(const unsigned long long*)&xs[b * 256 + d];
            unsigned long long x23 = *(const unsigned long long*)&xs[b * 256 + d + 2];
            accp[b] = fma2(x01, wp01, accp[b]);
            accp[b] = fma2(x23, wp23, accp[b]);
        }
    }
#pragma unroll
    for (int b = 0; b < 16; b++)
        g_proj_part[((c * 16 + b) * 48 + n) * 128 + tid] = hadd2(accp[b]);

    // ---- ticket (writes -> fence -> SYNC -> atomic): last block reduces ----
    __threadfence();
    __syncthreads();
    __shared__ unsigned int isLast;
    if (tid == 0) isLast = (atomicAdd(&g_tick_n[n], 1) == 15);
    __syncthreads();
    if (!isLast) return;
    if (tid == 0) g_tick_n[n] = 0;
    for (int b = 0; b < 16; b++) {
        float s = 0.f;
#pragma unroll
        for (int cc = 0; cc < 16; cc++)
            s += __ldcg(&g_proj_part[((cc * 16 + b) * 48 + n) * 128 + tid]);
        g_proj[(b * 48 + n) * 128 + tid] = s;
        if (n >= 32 && n < 40)
            out[KC_OFF + ((long long)(b * 8 + n - 32) * NM1 + NM) * 128 + tid] = s;
        else if (n >= 40)
            out[VC_OFF + ((long long)(b * 8 + n - 40) * NM1 + NM) * 128 + tid] = s;
    }
}

// ---------------------------------------------------------------------------
// K2 (fused, R5 version): single pass per (b,g,chunk): stream K&V -> Kc/Vc,
// logits via warp reduce, e = exp(logit) (bounded logits), accumulate s and
// e*V. Depth-1 software prefetch. Last chunk-block per (b,g) combines -> g_o.
// ---------------------------------------------------------------------------
__global__ void __launch_bounds__(256, 3)
k_fused(const float* __restrict__ prevK,
        const float* __restrict__ prevV,
        float* __restrict__ out) {
    int bg = blockIdx.x >> 6;
    int chunk = blockIdx.x & 63;
    int b = bg >> 3, g = bg & 7;
    int tid = threadIdx.x, warp = tid >> 5, lane = tid & 31;
    int m0 = chunk * 128;

    float4 q0 = *(const float4*)&g_proj[(b * 48 + 0 * 8 + g) * 128 + lane * 4];
    float4 q1 = *(const float4*)&g_proj[(b * 48 + 1 * 8 + g) * 128 + lane * 4];
    float4 q2 = *(const float4*)&g_proj[(b * 48 + 2 * 8 + g) * 128 + lane * 4];
    float4 q3 = *(const float4*)&g_proj[(b * 48 + 3 * 8 + g) * 128 + lane * 4];

    const float4* srcK = (const float4*)(prevK + ((size_t)bg * NM + m0) * 128);
    const float4* srcV = (const float4*)(prevV + ((size_t)bg * NM + m0) * 128);
    float4* dstK = (float4*)(out + KC_OFF + ((long long)bg * NM1 + m0) * 128);
    float4* dstV = (float4*)(out + VC_OFF + ((long long)bg * NM1 + m0) * 128);

    float4 a0 = {0, 0, 0, 0}, a1 = a0, a2 = a0, a3 = a0;
    float s0 = 0.f, s1 = 0.f, s2 = 0.f, s3 = 0.f;

    int r = warp;
    float4 kv = __ldcs(srcK + r * 32 + lane);
    float4 vv = __ldcs(srcV + r * 32 + lane);
#pragma unroll
    for (int it = 0; it < 16; it++) {
        float4 kn = {0, 0, 0, 0}, vn = {0, 0, 0, 0};
        if (it < 15) {                        // prefetch next row
            kn = __ldcs(srcK + (r + 8) * 32 + lane);
            vn = __ldcs(srcV + (r + 8) * 32 + lane);
        }
        __stcs(dstK + r * 32 + lane, kv);
        __stcs(dstV + r * 32 + lane, vv);
        float l0 = kv.x * q0.x + kv.y * q0.y + kv.z * q0.z + kv.w * q0.w;
        float l1 = kv.x * q1.x + kv.y * q1.y + kv.z * q1.z + kv.w * q1.w;
        float l2 = kv.x * q2.x + kv.y * q2.y + kv.z * q2.z + kv.w * q2.w;
        float l3 = kv.x * q3.x + kv.y * q3.y + kv.z * q3.z + kv.w * q3.w;
#pragma unroll
        for (int off = 16; off > 0; off >>= 1) {
            l0 += __shfl_xor_sync(0xffffffffu, l0, off);
            l1 += __shfl_xor_sync(0xffffffffu, l1, off);
            l2 += __shfl_xor_sync(0xffffffffu, l2, off);
            l3 += __shfl_xor_sync(0xffffffffu, l3, off);
        }
        float e0 = __expf(l0), e1 = __expf(l1), e2 = __expf(l2), e3 = __expf(l3);
        s0 += e0; s1 += e1; s2 += e2; s3 += e3;
        a0.x += e0 * vv.x; a0.y += e0 * vv.y; a0.z += e0 * vv.z; a0.w += e0 * vv.w;
        a1.x += e1 * vv.x; a1.y += e1 * vv.y; a1.z += e1 * vv.z; a1.w += e1 * vv.w;
        a2.x += e2 * vv.x; a2.y += e2 * vv.y; a2.z += e2 * vv.z; a2.w += e2 * vv.w;
        a3.x += e3 * vv.x; a3.y += e3 * vv.y; a3.z += e3 * vv.z; a3.w += e3 * vv.w;
        kv = kn; vv = vn; r += 8;
    }

    // Block-level merge of 8 warp partials
    __shared__ __align__(16) float accs[8 * 512];
    __shared__ float ssum[8 * 4];
    float4* ap = (float4*)&accs[warp * 512];
    ap[lane] = a0; ap[32 + lane] = a1; ap[64 + lane] = a2; ap[96 + lane] = a3;
    if (lane == 0) {
        ssum[warp * 4 + 0] = s0; ssum[warp * 4 + 1] = s1;
        ssum[warp * 4 + 2] = s2; ssum[warp * 4 + 3] = s3;
    }
    __syncthreads();
    size_t pbase = ((size_t)bg * 64 + chunk) * 512;
    for (int idx = tid; idx < 512; idx += 256) {
        float s = 0.f;
#pragma unroll
        for (int w = 0; w < 8; w++) s += accs[w * 512 + idx];
        g_part[pbase + idx] = s;
    }
    if (tid < 4) {
        float t = 0.f;
#pragma unroll
        for (int w = 0; w < 8; w++) t += ssum[w * 4 + tid];
        g_stats[((size_t)bg * 64 + chunk) * 4 + tid] = t;
    }

    // ---- ticket (writes -> fence -> SYNC -> atomic): last block combines ----
    __threadfence();
    __syncthreads();
    __shared__ unsigned int isLast;
    if (tid == 0) isLast = (atomicAdd(&g_tick_bg[bg], 1) == 63);
    __syncthreads();
    if (!isLast) return;
    if (tid == 0) g_tick_bg[bg] = 0;

    __shared__ float s_en[4], s_den[4];
    if (warp < 4) {   // new-token logit per head ri = warp
        float4 qq = *(const float4*)&g_proj[(b * 48 + warp * 8 + g) * 128 + lane * 4];
        float4 kk = *(const float4*)&g_proj[(b * 48 + 32 + g) * 128 + lane * 4];
        float p = qq.x * kk.x + qq.y * kk.y + qq.z * kk.z + qq.w * kk.w;
#pragma unroll
        for (int off = 16; off > 0; off >>= 1)
            p += __shfl_xor_sync(0xffffffffu, p, off);
        if (lane == 0) s_en[warp] = __expf(p);
    }
    __syncthreads();
    if (tid < 4) {
        float den = s_en[tid];
#pragma unroll 8
        for (int c2 = 0; c2 < 64; c2++)
            den += __ldcg(&g_stats[((size_t)bg * 64 + c2) * 4 + tid]);
        s_den[tid] = den;
    }
    __syncthreads();
    for (int idx = tid; idx < 512; idx += 256) {
        int ri = idx >> 7, v = idx & 127;
        float acc = s_en[ri] * g_proj[(b * 48 + 40 + g) * 128 + v];
        size_t base = (size_t)bg * 64 * 512 + idx;
#pragma unroll 8
        for (int c2 = 0; c2 < 64; c2++)
            acc += __ldcg(&g_part[base + (size_t)c2 * 512]);
        g_o[(b * 32 + ri * 8 + g) * 128 + v] = acc / s_den[ri];
    }
}

// ---------------------------------------------------------------------------
// K3: y[b,d] = sum_hv o[b,hv] * Wo[hv,d]. grid (32,16), block 256 = 2 halves
// x 128 d. Each half covers 128 hv-values; block writes 2 of 32 partials.
// Last block per d0 reduces and writes y. (memory-bound: 256-thr helps)
// ---------------------------------------------------------------------------
__global__ void k_y(const float* __restrict__ Wo, float* __restrict__ out) {
    int d0 = blockIdx.x * 128;
    int c = blockIdx.y;
    int tid = threadIdx.x;
    int half = tid >> 7;
    int dd = tid & 127;
    int hv0 = c * 256 + half * 128;
    __shared__ __align__(16) float os[2 * 16 * 128];
    for (int idx = tid; idx < 2 * 16 * 128; idx += 256) {
        int hh = idx >> 11, rem = idx & 2047;
        int b = rem >> 7, j = rem & 127;
        os[idx] = g_o[b * 4096 + c * 256 + hh * 128 + j];
    }
    __syncthreads();
    const float* oh = os + half * 2048;
    unsigned long long accp[16];
#pragma unroll
    for (int b = 0; b < 16; b++) accp[b] = 0ull;
    for (int j = 0; j < 128; j += 4) {
        float w0 = Wo[(size_t)(hv0 + j + 0) * 4096 + d0 + dd];
        float w1 = Wo[(size_t)(hv0 + j + 1) * 4096 + d0 + dd];
        float w2 = Wo[(size_t)(hv0 + j + 2) * 4096 + d0 + dd];
        float w3 = Wo[(size_t)(hv0 + j + 3) * 4096 + d0 + dd];
        unsigned long long wp01 = pack2(w0, w1);
        unsigned long long wp23 = pack2(w2, w3);
#pragma unroll
        for (int b = 0; b < 16; b++) {
            unsigned long long o01 = *(const unsigned long long*)&oh[b * 128 + j];
            unsigned long long o23 = *(const unsigned long long*)&oh[b * 128 + j + 2];
            accp[b] = fma2(o01, wp01, accp[b]);
            accp[b] = fma2(o23, wp23, accp[b]);
        }
    }
    int cc_out = c * 2 + half;
#pragma unroll
    for (int b = 0; b < 16; b++)
        g_ypart[(cc_out * 16 + b) * 4096 + d0 + dd] = hadd2(accp[b]);

    // ---- ticket (writes -> fence -> SYNC -> atomic): last block writes y ----
    __threadfence();
    __syncthreads();
    __shared__ unsigned int isLast;
    if (tid == 0) isLast = (atomicAdd(&g_tick_y[blockIdx.x], 1) == 15);
    __syncthreads();
    if (!isLast) return;
    if (tid == 0) g_tick_y[blockIdx.x] = 0;
    if (tid < 128) {
        for (int b = 0; b < 16; b++) {
            float s = 0.f;
#pragma unroll
            for (int cc = 0; cc < 32; cc++)
                s += __ldcg(&g_ypart[(cc * 16 + b) * 4096 + d0 + tid]);
            out[b * ND + d0 + tid] = s;
        }
    }
}

extern "C" void kernel_launch(void* const* d_in, const int* in_sizes, int n_in,
                              void* d_out, int out_size) {
    const float* x     = (const float*)d_in[0];
    const float* prevK = (const float*)d_in[1];
    const float* prevV = (const float*)d_in[2];
    const float* Wq    = (const float*)d_in[3];
    const float* Wk    = (const float*)d_in[4];
    const float* Wv    = (const float*)d_in[5];
    const float* Wo    = (const float*)d_in[6];
    float* out = (float*)d_out;

    k_proj<<<dim3(48, 16), 128>>>(x, Wq, Wk, Wv, out);
    k_fused<<<128 * 64, 256>>>(prevK, prevV, out);
    k_y<<<dim3(32, 16), 256>>>(Wo, out);
}